// round 6
// baseline (speedup 1.0000x reference)
#include <cuda_runtime.h>
#include <cstdint>

#define Bq 256
#define Tq 64
#define Nq 128
#define Hq 512
#define Kq 640   // Nq + Hq
#define Gq 2048  // 4*Hq
#define NBLK 128
#define NTHR 256
#define SROW 72              // smem row stride (floats), interleaved (hi,lo) pairs
#define SBUFF (64 * SROW)    // floats per matrix per buffer
#define DSMEM (4 * SBUFF * 4)  // bytes: {A,W} x 2 buffers = 73728

// ---------------- device scratch ----------------
__device__ __align__(16) float g_z2[Bq * Nq * Tq];  // (B,N,T)
__device__ __align__(16) float g_Wi[2 * Gq * Kq];   // [j'][k][{hi,lo}] tf32 split, j'=h*4+g
__device__ __align__(16) float g_bias[Gq];
__device__ __align__(16) float g_A[2][Bq * Kq];     // double-buffered [wx(128)|h(512)]
__device__ __align__(16) float g_C[Bq * Hq];
__device__ unsigned g_bar_count;
__device__ volatile unsigned g_bar_gen;

__device__ __forceinline__ float tanh_approx(float x) {
    float y;
    asm("tanh.approx.f32 %0, %1;" : "=f"(y) : "f"(x));
    return y;
}
__device__ __forceinline__ uint32_t tf32r(float f) {
    uint32_t u;
    asm("cvt.rna.tf32.f32 %0, %1;" : "=r"(u) : "f"(f));
    return u;
}

#define MMA_TF32(c, a0, a1, a2, a3, b0, b1)                              \
    asm volatile(                                                        \
        "mma.sync.aligned.m16n8k8.row.col.f32.tf32.tf32.f32 "            \
        "{%0,%1,%2,%3},{%4,%5,%6,%7},{%8,%9},{%0,%1,%2,%3};"             \
        : "+f"((c)[0]), "+f"((c)[1]), "+f"((c)[2]), "+f"((c)[3])         \
        : "r"(a0), "r"(a1), "r"(a2), "r"(a3), "r"(b0), "r"(b1))

__device__ __forceinline__ void grid_bar() {
    __syncthreads();
    if (threadIdx.x == 0) {
        __threadfence();
        unsigned gen = g_bar_gen;
        unsigned old = atomicInc(&g_bar_count, NBLK - 1);
        if (old == NBLK - 1) {
            g_bar_gen = gen + 1;
        } else {
            while (g_bar_gen == gen) __nanosleep(64);
        }
        __threadfence();
    }
    __syncthreads();
}

// ---------------- GEMM helpers ----------------
__device__ __forceinline__ void ld_a(float4 ra[2], const float* Ar, int bm, int kb, int tid) {
#pragma unroll
    for (int l = 0; l < 2; l++) {
        int idx = tid + l * 256;
        int row = idx >> 3, k4 = idx & 7;
        ra[l] = *(const float4*)(Ar + (bm + row) * Kq + kb + k4 * 4);
    }
}
__device__ __forceinline__ void ld_w(float4 rw[4], int jb, int kb, int tid) {
#pragma unroll
    for (int l = 0; l < 4; l++) {
        int idx = tid + l * 256;
        int row = idx >> 4, kq = idx & 15;
        rw[l] = *(const float4*)(g_Wi + ((jb + row) * Kq + kb) * 2 + kq * 4);
    }
}
__device__ __forceinline__ void st_ab(float* pA, float* pW, const float4 ra[2],
                                      const float4 rw[4], int tid) {
#pragma unroll
    for (int l = 0; l < 2; l++) {
        int idx = tid + l * 256;
        int row = idx >> 3, k4 = idx & 7;
        float h0 = __uint_as_float(tf32r(ra[l].x));
        float h1 = __uint_as_float(tf32r(ra[l].y));
        float h2 = __uint_as_float(tf32r(ra[l].z));
        float h3 = __uint_as_float(tf32r(ra[l].w));
        float l0 = __uint_as_float(tf32r(ra[l].x - h0));
        float l1 = __uint_as_float(tf32r(ra[l].y - h1));
        float l2 = __uint_as_float(tf32r(ra[l].z - h2));
        float l3 = __uint_as_float(tf32r(ra[l].w - h3));
        *(float4*)(pA + row * SROW + k4 * 8) = make_float4(h0, l0, h1, l1);
        *(float4*)(pA + row * SROW + k4 * 8 + 4) = make_float4(h2, l2, h3, l3);
    }
#pragma unroll
    for (int l = 0; l < 4; l++) {
        int idx = tid + l * 256;
        int row = idx >> 4, kq = idx & 15;
        *(float4*)(pW + row * SROW + kq * 4) = rw[l];
    }
}
__device__ __forceinline__ void mma_chunk(float (&cacc)[2][2][4], const float* pA,
                                          const float* pW, int wm, int wn, int gid, int tig) {
#pragma unroll
    for (int k8 = 0; k8 < 4; k8++) {
        int c0 = k8 * 8 + tig, c1 = c0 + 4;
        uint32_t ah[2][4], al[2][4];
#pragma unroll
        for (int mt = 0; mt < 2; mt++) {
            const float* rp = pA + (wm + mt * 16 + gid) * SROW;
            float2 p00 = *(const float2*)(rp + 2 * c0);
            float2 p10 = *(const float2*)(rp + 8 * SROW + 2 * c0);
            float2 p01 = *(const float2*)(rp + 2 * c1);
            float2 p11 = *(const float2*)(rp + 8 * SROW + 2 * c1);
            ah[mt][0] = __float_as_uint(p00.x); al[mt][0] = __float_as_uint(p00.y);
            ah[mt][1] = __float_as_uint(p10.x); al[mt][1] = __float_as_uint(p10.y);
            ah[mt][2] = __float_as_uint(p01.x); al[mt][2] = __float_as_uint(p01.y);
            ah[mt][3] = __float_as_uint(p11.x); al[mt][3] = __float_as_uint(p11.y);
        }
#pragma unroll
        for (int nt = 0; nt < 2; nt++) {
            const float* np = pW + (wn + nt * 8 + gid) * SROW;
            float2 q0 = *(const float2*)(np + 2 * c0);
            float2 q1 = *(const float2*)(np + 2 * c1);
            uint32_t bh0 = __float_as_uint(q0.x), bl0 = __float_as_uint(q0.y);
            uint32_t bh1 = __float_as_uint(q1.x), bl1 = __float_as_uint(q1.y);
#pragma unroll
            for (int mt = 0; mt < 2; mt++) {
                MMA_TF32(cacc[mt][nt], ah[mt][0], ah[mt][1], ah[mt][2], ah[mt][3], bh0, bh1);
                MMA_TF32(cacc[mt][nt], ah[mt][0], ah[mt][1], ah[mt][2], ah[mt][3], bl0, bl1);
                MMA_TF32(cacc[mt][nt], al[mt][0], al[mt][1], al[mt][2], al[mt][3], bh0, bh1);
            }
        }
    }
}

// ---------------- single persistent kernel ----------------
__global__ __launch_bounds__(NTHR) void main_kernel(
    const float* __restrict__ dx, const float* __restrict__ Wa1,
    const float* __restrict__ ba1, const float* __restrict__ Wa2,
    const float* __restrict__ ba2, const float* __restrict__ Wa3,
    const float* __restrict__ ba3, const float* __restrict__ Wih,
    const float* __restrict__ Whh, const float* __restrict__ bih,
    const float* __restrict__ bhh, float* __restrict__ out) {
    extern __shared__ float dyn[];
    float* bufA[2] = {dyn, dyn + 2 * SBUFF};
    float* bufW[2] = {dyn + SBUFF, dyn + 3 * SBUFF};

    __shared__ float hs[2][1024];
    __shared__ float z1s[2][64];
    __shared__ float wa3s[64];
    __shared__ float red[2][4];

    const int cta = blockIdx.x, tid = threadIdx.x;
    const int b0 = cta * 2;
    // phase B ids
    const int cm = cta >> 5, cn = cta & 31;
    const int bm = cm * 64, jb = cn * 64;
    const int wid = tid >> 5, lane = tid & 31;
    const int wm = (wid >> 2) * 32, wn = (wid & 3) * 16;
    const int gid = lane >> 2, tig = lane & 3;

    // ================= in-kernel prep =================
    {
        const int gtid = cta * NTHR + tid, gstr = NBLK * NTHR;
        for (int idx = gtid; idx < Gq * Kq; idx += gstr) {
            int jp = idx / Kq, k = idx - jp * Kq;
            int hh = jp >> 2, gg = jp & 3, j = gg * Hq + hh;
            float v = (k < Nq) ? Wih[j * Nq + k] : Whh[j * Hq + (k - Nq)];
            float hi = __uint_as_float(tf32r(v));
            g_Wi[2 * idx] = hi;
            g_Wi[2 * idx + 1] = __uint_as_float(tf32r(v - hi));
        }
        for (int idx = gtid; idx < Gq; idx += gstr) {
            int hh = idx >> 2, gg = idx & 3, j = gg * Hq + hh;
            g_bias[idx] = bih[j] + bhh[j];
        }
        for (int idx = gtid; idx < Bq * Kq; idx += gstr) {
            g_A[0][idx] = 0.f;
            g_A[1][idx] = 0.f;
        }
        for (int idx = gtid; idx < Bq * Hq; idx += gstr) g_C[idx] = 0.f;
        // z2 for this CTA's two batches, staging dx tile in dynamic smem
        float* sdx = dyn;
        for (int bb = 0; bb < 2; bb++) {
            int b = b0 + bb;
            __syncthreads();
            for (int i = tid; i < Tq * Nq / 4; i += NTHR)
                ((float4*)sdx)[i] = ((const float4*)(dx + b * Tq * Nq))[i];
            __syncthreads();
            for (int o = tid; o < Nq * Tq; o += NTHR) {
                int s = o & 63, n = o >> 6;
                float acc = 0.f;
#pragma unroll 8
                for (int tt = 0; tt < Tq; tt++) acc += sdx[tt * Nq + n] * __ldg(&Wa2[s * Tq + tt]);
                g_z2[(b * Nq + n) * Tq + s] = acc + ba2[s];
            }
        }
        grid_bar();
    }

    if (tid < 64) wa3s[tid] = Wa3[tid];
    const float ba3v = ba3[0];
    const int pa_s = tid >> 2, pa_part = tid & 3;
    const float ba1v = ba1[pa_s];

    for (int t = 0; t < Tq; t++) {
        const int rb = t & 1;
        const float* Ar = g_A[rb];
        float* Aw = g_A[rb ^ 1];

        // ================= phase A: z1 + attention =================
        {
            int bb = tid >> 7, k4 = (tid & 127) * 4;
            *(float4*)&hs[bb][k4] = *(const float4*)(Ar + (b0 + bb) * Kq + Nq + k4);
            *(float4*)&hs[bb][512 + k4] = *(const float4*)(g_C + (b0 + bb) * Hq + k4);
        }
        __syncthreads();
        {
            const float* wr = Wa1 + pa_s * 1024 + pa_part * 256;
            const float* h0 = hs[0] + pa_part * 256;
            const float* h1 = hs[1] + pa_part * 256;
            float acc0 = 0.f, acc1 = 0.f;
#pragma unroll 8
            for (int k = 0; k < 256; k += 4) {
                float4 w = *(const float4*)(wr + k);
                acc0 += h0[k] * w.x + h0[k + 1] * w.y + h0[k + 2] * w.z + h0[k + 3] * w.w;
                acc1 += h1[k] * w.x + h1[k + 1] * w.y + h1[k + 2] * w.z + h1[k + 3] * w.w;
            }
            acc0 += __shfl_xor_sync(0xffffffffu, acc0, 1);
            acc0 += __shfl_xor_sync(0xffffffffu, acc0, 2);
            acc1 += __shfl_xor_sync(0xffffffffu, acc1, 1);
            acc1 += __shfl_xor_sync(0xffffffffu, acc1, 2);
            if (pa_part == 0) {
                z1s[0][pa_s] = acc0 + ba1v;
                z1s[1][pa_s] = acc1 + ba1v;
            }
        }
        __syncthreads();
        {
            int bb = tid >> 7, n = tid & 127;
            int b = b0 + bb;
            const float4* z2r = (const float4*)(g_z2 + (b * Nq + n) * Tq);
            float e = ba3v;
#pragma unroll
            for (int s4 = 0; s4 < Tq / 4; s4++) {
                float4 z = z2r[s4];
                int s = s4 * 4;
                e += tanh_approx(z1s[bb][s + 0] + z.x) * wa3s[s + 0];
                e += tanh_approx(z1s[bb][s + 1] + z.y) * wa3s[s + 1];
                e += tanh_approx(z1s[bb][s + 2] + z.z) * wa3s[s + 2];
                e += tanh_approx(z1s[bb][s + 3] + z.w) * wa3s[s + 3];
            }
            float m = e;
            for (int o = 16; o > 0; o >>= 1) m = fmaxf(m, __shfl_xor_sync(0xffffffffu, m, o));
            if (lane == 0) red[bb][wid & 3] = m;
            __syncthreads();
            m = fmaxf(fmaxf(red[bb][0], red[bb][1]), fmaxf(red[bb][2], red[bb][3]));
            float p = __expf(e - m);
            float sum = p;
            for (int o = 16; o > 0; o >>= 1) sum += __shfl_xor_sync(0xffffffffu, sum, o);
            __syncthreads();
            if (lane == 0) red[bb][wid & 3] = sum;
            __syncthreads();
            sum = red[bb][0] + red[bb][1] + red[bb][2] + red[bb][3];
            float w = p / sum;
            g_A[rb][b * Kq + n] = w * dx[(b * Tq + t) * Nq + n];
        }

        // ================= phase B: GEMM, h-chunks first =================
        float cacc[2][2][4] = {};
        float4 ra[2], rw[4];
        ld_a(ra, Ar, bm, 128, tid);
        ld_w(rw, jb, 128, tid);
        for (int i = 0; i < 16; i++) {
            st_ab(bufA[i & 1], bufW[i & 1], ra, rw, tid);
            __syncthreads();
            if (i < 15) {
                ld_a(ra, Ar, bm, 160 + 32 * i, tid);
                ld_w(rw, jb, 160 + 32 * i, tid);
            }
            mma_chunk(cacc, bufA[i & 1], bufW[i & 1], wm, wn, gid, tig);
        }
        grid_bar();  // wx from ALL CTAs now visible
        ld_a(ra, Ar, bm, 0, tid);
        ld_w(rw, jb, 0, tid);
        for (int i = 16; i < 20; i++) {
            st_ab(bufA[i & 1], bufW[i & 1], ra, rw, tid);
            __syncthreads();
            if (i < 19) {
                ld_a(ra, Ar, bm, 32 * (i - 15), tid);
                ld_w(rw, jb, 32 * (i - 15), tid);
            }
            mma_chunk(cacc, bufA[i & 1], bufW[i & 1], wm, wn, gid, tig);
        }

        // fused LSTM epilogue
#pragma unroll
        for (int mt = 0; mt < 2; mt++) {
#pragma unroll
            for (int nt = 0; nt < 2; nt++) {
                float v0 = cacc[mt][nt][0], v1 = cacc[mt][nt][1];
                float v2 = cacc[mt][nt][2], v3 = cacc[mt][nt][3];
                float p0 = __shfl_xor_sync(0xffffffffu, v0, 1);
                float p1 = __shfl_xor_sync(0xffffffffu, v1, 1);
                float p2 = __shfl_xor_sync(0xffffffffu, v2, 1);
                float p3 = __shfl_xor_sync(0xffffffffu, v3, 1);
                if ((tig & 1) == 0) {
                    int jcol = jb + wn + nt * 8 + 2 * tig;
                    int h = jcol >> 2;
                    float4 bias = *(const float4*)(g_bias + jcol);
                    int b = bm + wm + mt * 16 + gid;
#pragma unroll
                    for (int rr = 0; rr < 2; rr++) {
                        int bb = b + rr * 8;
                        float gi = (rr ? v2 : v0) + bias.x;
                        float gf = (rr ? v3 : v1) + bias.y;
                        float gg = (rr ? p2 : p0) + bias.z;
                        float go = (rr ? p3 : p1) + bias.w;
                        float co = g_C[bb * Hq + h];
                        float si = 1.f / (1.f + __expf(-gi));
                        float sf = 1.f / (1.f + __expf(-gf));
                        float so = 1.f / (1.f + __expf(-go));
                        float cn2 = sf * co + si * tanhf(gg);
                        float hn = so * tanhf(cn2);
                        g_C[bb * Hq + h] = cn2;
                        Aw[bb * Kq + Nq + h] = hn;
                        out[(bb * Tq + t) * Hq + h] = hn;
                    }
                }
            }
        }
        grid_bar();
    }
}

extern "C" void kernel_launch(void* const* d_in, const int* in_sizes, int n_in,
                              void* d_out, int out_size) {
    const float* dx  = (const float*)d_in[0];
    const float* Wa1 = (const float*)d_in[1];
    const float* ba1 = (const float*)d_in[2];
    const float* Wa2 = (const float*)d_in[3];
    const float* ba2 = (const float*)d_in[4];
    const float* Wa3 = (const float*)d_in[5];
    const float* ba3 = (const float*)d_in[6];
    const float* Wih = (const float*)d_in[7];
    const float* Whh = (const float*)d_in[8];
    const float* bih = (const float*)d_in[9];
    const float* bhh = (const float*)d_in[10];
    float* out = (float*)d_out;

    cudaFuncSetAttribute(main_kernel, cudaFuncAttributeMaxDynamicSharedMemorySize, DSMEM);
    main_kernel<<<NBLK, NTHR, DSMEM>>>(dx, Wa1, ba1, Wa2, ba2, Wa3, ba3, Wih, Whh, bih, bhh, out);
}